// round 12
// baseline (speedup 1.0000x reference)
#include <cuda_runtime.h>

// dwtHaar_2d: x (8,64,512,512) f32 -> 4 subbands (8,64,256,256) concatenated.
// Reflect pad left/top by 1, stride 2, kernel 2 => non-overlapping windows.
// out[s][bc][i][j], s in {LL, LH, HL, HH}.
//
// FINAL (R10 form): 4 output cols/thread (4x LDG.128 in, 4x STG.128 out,
// plain cache policy), 2 output rows per 128-thread block.
//
// Convergence evidence (R1..R10): every structurally distinct variant lands
// at 156 +/- 2 us wall / ~150 us ncu with DRAM 83-86%; ncu_dur x BW equals
// the provably-minimal 1.02 GB of traffic (each element read+written once).
// The kernel runs at the chip's mixed R/W HBM3e ceiling (~6.83 TB/s, 86% of
// read-peak spec). Cache hints (.cs on either path) regress; store width,
// CTA shape, and load/store phase batching are neutral. No further lever
// exists for this op.

namespace {
constexpr int H  = 512;
constexpr int W  = 512;
constexpr int Ho = 256;
constexpr int Wo = 256;
constexpr int BC = 8 * 64;                         // 512
constexpr long long SUB = (long long)BC * Ho * Wo; // elements per subband
}

__global__ __launch_bounds__(128) void dwt_haar_kernel(
    const float* __restrict__ x, float* __restrict__ out)
{
    const int t    = threadIdx.x;            // 0..127
    const int half = t >> 6;                 // which of the 2 output rows
    const int u    = t & 63;                 // 0..63: output cols [4u, 4u+4)
    const int i    = blockIdx.x * 2 + half;  // output row 0..255
    const int bc   = blockIdx.y;             // 0..511

    const float* base  = x + (size_t)bc * (H * W);
    const int    r_top = (i == 0) ? 1 : (2 * i - 1);  // reflect row -1 -> row 1
    const int    r_bot = 2 * i;

    const float* rowt = base + (size_t)r_top * W;
    const float* rowb = base + (size_t)r_bot * W;

    // 4 independent aligned 16B loads: input cols [8u, 8u+8) of both rows.
    const float4 t0 = reinterpret_cast<const float4*>(rowt)[2 * u];
    const float4 t1 = reinterpret_cast<const float4*>(rowt)[2 * u + 1];
    const float4 b0 = reinterpret_cast<const float4*>(rowb)[2 * u];
    const float4 b1 = reinterpret_cast<const float4*>(rowb)[2 * u + 1];

    // Left neighbor element (input col 8u-1) = previous thread's t1.w / b1.w.
    float lt = __shfl_up_sync(0xffffffffu, t1.w, 1);
    float lb = __shfl_up_sync(0xffffffffu, b1.w, 1);
    if ((t & 31) == 0) {
        if (u == 0) {            // col -1 reflects to col 1
            lt = t0.y;
            lb = b0.y;
        } else {                 // cross-warp lane: one scalar load (L1 hit)
            lt = rowt[8 * u - 1];
            lb = rowb[8 * u - 1];
        }
    }

    // e[-1..6] per row: window for output col 4u+p uses (e[2p-1], e[2p]).
    const float et[8] = {lt, t0.x, t0.y, t0.z, t0.w, t1.x, t1.y, t1.z};
    const float eb[8] = {lb, b0.x, b0.y, b0.z, b0.w, b1.x, b1.y, b1.z};

    float4 ll, lh, hl, hh;
    float* pll = &ll.x; float* plh = &lh.x; float* phl = &hl.x; float* phh = &hh.x;
    #pragma unroll
    for (int p = 0; p < 4; p++) {
        const float a = et[2 * p];     // top row, col 8u+2p-1
        const float b = et[2 * p + 1]; // top row, col 8u+2p
        const float c = eb[2 * p];     // bottom row
        const float d = eb[2 * p + 1];
        pll[p] = 0.5f * ( a + b + c + d);
        plh[p] = 0.5f * ( a + b - c - d);
        phl[p] = 0.5f * (-a + b - c + d);
        phh[p] = 0.5f * ( a - b - c + d);
    }

    const size_t obase = (size_t)bc * (Ho * Wo) + (size_t)i * Wo + 4 * u;
    *reinterpret_cast<float4*>(out + obase)           = ll;
    *reinterpret_cast<float4*>(out + SUB + obase)     = lh;
    *reinterpret_cast<float4*>(out + 2 * SUB + obase) = hl;
    *reinterpret_cast<float4*>(out + 3 * SUB + obase) = hh;
}

extern "C" void kernel_launch(void* const* d_in, const int* in_sizes, int n_in,
                              void* d_out, int out_size)
{
    const float* x = (const float*)d_in[0];
    float* out     = (float*)d_out;

    dim3 grid(Ho / 2, BC);   // (128, 512)
    dim3 block(128);
    dwt_haar_kernel<<<grid, block>>>(x, out);
}

// round 14
// speedup vs baseline: 1.0012x; 1.0012x over previous
#include <cuda_runtime.h>

// dwtHaar_2d: x (8,64,512,512) f32 -> 4 subbands (8,64,256,256) concatenated.
// Reflect pad left/top by 1, stride 2, kernel 2 => non-overlapping windows.
// out[s][bc][i][j], s in {LL, LH, HL, HH}.
//
// FINAL (R6 form, best measured wall: 156.1 us): 2 output cols/thread,
// 2 output rows per 256-thread block, plain cache policy.
//
// Convergence evidence (12 rounds): ncu_dur x achieved-BW equals the
// provably-minimal 1.02 GB of traffic (every input element read once,
// every output element written once; disjoint stride-2 windows admit no
// reuse). Kernel runs at the chip's mixed R/W HBM3e ceiling (~6.83 TB/s,
// ~86% of 8 TB/s read-peak spec); DRAM is the only pipe above 41%.
// Swept and rejected: .cs cache hints on either path (regress 2-10 us),
// STG.128 vs STG.64 (neutral), 1/2/4 rows per block (neutral), 128 vs 256
// threads (neutral), front-batched load/store phases for R/W turnaround
// (neutral). No further lever exists for this op on this chip.

namespace {
constexpr int H  = 512;
constexpr int W  = 512;
constexpr int Ho = 256;
constexpr int Wo = 256;
constexpr int BC = 8 * 64;                         // 512
constexpr long long SUB = (long long)BC * Ho * Wo; // elements per subband
}

__global__ __launch_bounds__(256) void dwt_haar_kernel(
    const float* __restrict__ x, float* __restrict__ out)
{
    const int t    = threadIdx.x & 127;          // 0..127 : output cols 2t, 2t+1
    const int half = threadIdx.x >> 7;           // 0..1   : which output row
    const int i    = blockIdx.x * 2 + half;      // 0..255 : output row
    const int bc   = blockIdx.y;                 // 0..511

    const float* base = x + (size_t)bc * (H * W);
    const int r_top = (i == 0) ? 1 : (2 * i - 1);   // reflect row -1 -> row 1
    const int r_bot = 2 * i;

    const float* rowt = base + (size_t)r_top * W;
    const float* rowb = base + (size_t)r_bot * W;

    // Aligned 16B loads: cols [4t .. 4t+3] of each row.
    const float4 vt = reinterpret_cast<const float4*>(rowt)[t];
    const float4 vb = reinterpret_cast<const float4*>(rowb)[t];

    // Left neighbor element (col 4t-1) via warp shuffle; fix up warp-edge lanes.
    float lt = __shfl_up_sync(0xffffffffu, vt.w, 1);
    float lb = __shfl_up_sync(0xffffffffu, vb.w, 1);
    if ((t & 31) == 0) {
        if (t == 0) {            // col -1 reflects to col 1
            lt = vt.y;
            lb = vb.y;
        } else {                 // cross-warp: one scalar load (L1 hit)
            lt = rowt[4 * t - 1];
            lb = rowb[4 * t - 1];
        }
    }

    // Output col j0 = 2t: window cols (4t-1, 4t). Output col j1 = 2t+1: cols (4t+1, 4t+2).
    const float a0 = lt,   b0 = vt.x, c0 = lb,   d0 = vb.x;
    const float a1 = vt.y, b1 = vt.z, c1 = vb.y, d1 = vb.z;

    float2 ll, lh, hl, hh;
    ll.x = 0.5f * ( a0 + b0 + c0 + d0);
    ll.y = 0.5f * ( a1 + b1 + c1 + d1);
    lh.x = 0.5f * ( a0 + b0 - c0 - d0);
    lh.y = 0.5f * ( a1 + b1 - c1 - d1);
    hl.x = 0.5f * (-a0 + b0 - c0 + d0);
    hl.y = 0.5f * (-a1 + b1 - c1 + d1);
    hh.x = 0.5f * ( a0 - b0 - c0 + d0);
    hh.y = 0.5f * ( a1 - b1 - c1 + d1);

    const size_t obase = (size_t)bc * (Ho * Wo) + (size_t)i * Wo + 2 * t;
    *reinterpret_cast<float2*>(out + obase)           = ll;
    *reinterpret_cast<float2*>(out + SUB + obase)     = lh;
    *reinterpret_cast<float2*>(out + 2 * SUB + obase) = hl;
    *reinterpret_cast<float2*>(out + 3 * SUB + obase) = hh;
}

extern "C" void kernel_launch(void* const* d_in, const int* in_sizes, int n_in,
                              void* d_out, int out_size)
{
    const float* x = (const float*)d_in[0];
    float* out     = (float*)d_out;

    dim3 grid(Ho / 2, BC);   // (128, 512)
    dim3 block(256);
    dwt_haar_kernel<<<grid, block>>>(x, out);
}

// round 16
// speedup vs baseline: 1.0129x; 1.0117x over previous
#include <cuda_runtime.h>

// dwtHaar_2d: x (8,64,512,512) f32 -> 4 subbands (8,64,256,256) concatenated.
// Reflect pad left/top by 1, stride 2, kernel 2 => non-overlapping windows.
// out[s][bc][i][j], s in {LL, LH, HL, HH}.
//
// R14: last untested structural cell -- 512-thread blocks, 4 output rows
// per block, per-warp access pattern identical to the best variants
// (2 output cols/thread, LDG.128 x2 in, STG.64 x4 out, plain policy).
// 32768 CTAs total. Everything else measured at the mixed R/W HBM
// roofline (~149.3 us ncu, 86% DRAM, 6.84 TB/s on minimal 1.02 GB traffic).

namespace {
constexpr int H  = 512;
constexpr int W  = 512;
constexpr int Ho = 256;
constexpr int Wo = 256;
constexpr int BC = 8 * 64;                         // 512
constexpr int RPB = 4;                             // output rows per block
constexpr long long SUB = (long long)BC * Ho * Wo; // elements per subband
}

__global__ __launch_bounds__(512) void dwt_haar_kernel(
    const float* __restrict__ x, float* __restrict__ out)
{
    const int t    = threadIdx.x & 127;          // 0..127 : output cols 2t, 2t+1
    const int sub  = threadIdx.x >> 7;           // 0..3   : which output row
    const int i    = blockIdx.x * RPB + sub;     // 0..255 : output row
    const int bc   = blockIdx.y;                 // 0..511

    const float* base = x + (size_t)bc * (H * W);
    const int r_top = (i == 0) ? 1 : (2 * i - 1);   // reflect row -1 -> row 1
    const int r_bot = 2 * i;

    const float* rowt = base + (size_t)r_top * W;
    const float* rowb = base + (size_t)r_bot * W;

    // Aligned 16B loads: cols [4t .. 4t+3] of each row.
    const float4 vt = reinterpret_cast<const float4*>(rowt)[t];
    const float4 vb = reinterpret_cast<const float4*>(rowb)[t];

    // Left neighbor element (col 4t-1) via warp shuffle; fix up warp-edge lanes.
    float lt = __shfl_up_sync(0xffffffffu, vt.w, 1);
    float lb = __shfl_up_sync(0xffffffffu, vb.w, 1);
    if ((t & 31) == 0) {
        if (t == 0) {            // col -1 reflects to col 1
            lt = vt.y;
            lb = vb.y;
        } else {                 // cross-warp: one scalar load (L1 hit)
            lt = rowt[4 * t - 1];
            lb = rowb[4 * t - 1];
        }
    }

    // Output col j0 = 2t: window cols (4t-1, 4t). Output col j1 = 2t+1: cols (4t+1, 4t+2).
    const float a0 = lt,   b0 = vt.x, c0 = lb,   d0 = vb.x;
    const float a1 = vt.y, b1 = vt.z, c1 = vb.y, d1 = vb.z;

    float2 ll, lh, hl, hh;
    ll.x = 0.5f * ( a0 + b0 + c0 + d0);
    ll.y = 0.5f * ( a1 + b1 + c1 + d1);
    lh.x = 0.5f * ( a0 + b0 - c0 - d0);
    lh.y = 0.5f * ( a1 + b1 - c1 - d1);
    hl.x = 0.5f * (-a0 + b0 - c0 + d0);
    hl.y = 0.5f * (-a1 + b1 - c1 + d1);
    hh.x = 0.5f * ( a0 - b0 - c0 + d0);
    hh.y = 0.5f * ( a1 - b1 - c1 + d1);

    const size_t obase = (size_t)bc * (Ho * Wo) + (size_t)i * Wo + 2 * t;
    *reinterpret_cast<float2*>(out + obase)           = ll;
    *reinterpret_cast<float2*>(out + SUB + obase)     = lh;
    *reinterpret_cast<float2*>(out + 2 * SUB + obase) = hl;
    *reinterpret_cast<float2*>(out + 3 * SUB + obase) = hh;
}

extern "C" void kernel_launch(void* const* d_in, const int* in_sizes, int n_in,
                              void* d_out, int out_size)
{
    const float* x = (const float*)d_in[0];
    float* out     = (float*)d_out;

    dim3 grid(Ho / RPB, BC);   // (64, 512)
    dim3 block(512);
    dwt_haar_kernel<<<grid, block>>>(x, out);
}